// round 3
// baseline (speedup 1.0000x reference)
#include <cuda_runtime.h>
#include <cstdint>
#include <cstddef>

// Residual Vector Quantizer: B=16,S=4096,D=128, Q=4 stages, K=512 codes.
// Bit-exact replication of the eager JAX/XLA-on-GPU reference:
//   cross : cuBLAS SGEMM order  -> ascending-d single-accumulator FMA chain
//   r2,c2 : rounded products + XLA vec2 row-reduce + shfl-down(16..1) tree
//   d2    : (r2 - 2*cross) + c2, explicit rounding ops, no contraction
//   argmin: min value, lowest index (order independent)
//   quantized: stage-ordered adds, then x + (quantized - x)
//
// Output buffer layout (float32):
//   [0, BSD)        quantized
//   [BSD, BSD+BSQ)  indices (as float)
//   [BSD+BSQ]       commitment loss * 0.25

#define Dd      128
#define Kk      512
#define Qq      4
#define MT      128   // tokens per CTA
#define KCH     64    // codewords per smem chunk
#define RS      132   // padded smem row stride (floats)
#define THREADS 256
#define MAXGRID 1024

// smem layout (floats):
//   residual   : 16960   (skewed rows)
//   cb buf0    : 8448
//   cb buf1    : 8448
//   idxAll     : 512 ints (4 stages x 128 tokens)
//   r2s        : 128
//   wsum       : 8
#define RES_FLOATS   16960
#define CB_FLOATS    8448
#define IDX_OFF      (RES_FLOATS + 2*CB_FLOATS)          // 33856
#define R2_OFF       (IDX_OFF + 512)                     // 34368
#define WSUM_OFF     (R2_OFF + 128)                      // 34496
#define SMEM_FLOATS  (WSUM_OFF + 8)                      // 34504
#define SMEM_BYTES   (SMEM_FLOATS * 4)

__device__ float g_c2[Qq * Kk];
__device__ float g_partials[MAXGRID];

__device__ __forceinline__ int roff(int t) { return t * RS + (t >> 3) * 4; }

#define CP16(dst, src) \
    asm volatile("cp.async.cg.shared.global [%0],[%1],16;" :: "r"(dst), "l"(src))
#define CP_COMMIT() asm volatile("cp.async.commit_group;")
#define CP_WAIT(n)  asm volatile("cp.async.wait_group %0;" :: "n"(n))

// XLA row-reduction emulation: lane partial (vec2, 2 iters, stride 32 float2s)
// then shfl-down tree 16,8,4,2,1. p2 = pointer to float2 row of 64 float2s.
// Products are rounded individually (eager mul kernel), adds are plain fadd.
__device__ __forceinline__ float xla_row_sumsq(const float2* p2, int lane) {
    float2 a = p2[lane];
    float2 b = p2[lane + 32];
    float p0 = __fmul_rn(a.x, a.x);
    float p1 = __fmul_rn(a.y, a.y);
    float q0 = __fmul_rn(b.x, b.x);
    float q1 = __fmul_rn(b.y, b.y);
    // acc.x = p0 + q0 ; acc.y = p1 + q1 ; scalar = acc.x + acc.y
    float part = __fadd_rn(__fadd_rn(p0, q0), __fadd_rn(p1, q1));
    #pragma unroll
    for (int off = 16; off >= 1; off >>= 1)
        part = __fadd_rn(part, __shfl_down_sync(0xffffffffu, part, off));
    return part;  // valid on lane 0
}

// ---------------------------------------------------------------------------
// c2[q*K+k] = XLA-ordered sum of squares of codebook row. One warp per row.
// ---------------------------------------------------------------------------
__global__ void c2_kernel(const float* __restrict__ cbks) {
    int warp = (blockIdx.x * blockDim.x + threadIdx.x) >> 5;
    int lane = threadIdx.x & 31;
    if (warp < Qq * Kk) {
        const float2* p2 = (const float2*)(cbks + (size_t)warp * Dd);
        float s = xla_row_sumsq(p2, lane);
        if (lane == 0) g_c2[warp] = s;
    }
}

// ---------------------------------------------------------------------------
// Main RVQ kernel. One CTA = 128 tokens, all 4 stages.
// ---------------------------------------------------------------------------
__global__ void __launch_bounds__(THREADS, 1)
rvq_kernel(const float* __restrict__ x, const float* __restrict__ cbks,
           float* __restrict__ out_q, float* __restrict__ out_idx, int has_idx)
{
    extern __shared__ float sm[];
    const int tid     = threadIdx.x;
    const int lane    = tid & 31;
    const int cta     = blockIdx.x;
    const int tokBase = cta * MT;

    float* res    = sm;
    int*   idxAll = (int*)(sm + IDX_OFF);
    float* r2s    = sm + R2_OFF;
    float* wsum   = sm + WSUM_OFF;
    const uint32_t sbase  = (uint32_t)__cvta_generic_to_shared(sm);
    const uint32_t cboff0 = (uint32_t)RES_FLOATS * 4u;
    const uint32_t cboff1 = (uint32_t)(RES_FLOATS + CB_FLOATS) * 4u;

    // Load x tile into smem residual (skewed layout)
    const float4* x4 = (const float4*)(x + (size_t)tokBase * Dd);
    for (int e = tid; e < MT * (Dd / 4); e += THREADS) {
        int t = e >> 5, d4 = e & 31;
        *(float4*)(res + roff(t) + d4 * 4) = x4[e];
    }
    __syncthreads();

    const int ty = tid >> 4;   // token group 0..15 (8 tokens each)
    const int tx = tid & 15;   // k group (4 codes each within 64-chunk)
    float lossAcc = 0.f;

    for (int stage = 0; stage < Qq; ++stage) {
        const float* cbg = cbks + (size_t)stage * Kk * Dd;

        // prefetch chunk 0 -> buf0 (overlaps with r2 phase)
        for (int e = tid; e < KCH * (Dd / 4); e += THREADS) {
            int kk = e >> 5, d4 = e & 31;
            uint32_t dst = sbase + cboff0 + (uint32_t)(kk * RS + d4 * 4) * 4u;
            CP16(dst, cbg + (size_t)kk * Dd + d4 * 4);
        }
        CP_COMMIT();

        // ---- r2 per token, XLA row-reduce order ----
        {
            int w = tid >> 5;  // warp 0..7, each handles 16 tokens
            for (int it = 0; it < 16; ++it) {
                int t = w * 16 + it;
                const float2* rp = (const float2*)(res + roff(t));
                float s = xla_row_sumsq(rp, lane);
                if (lane == 0) r2s[t] = s;
            }
        }
        __syncthreads();

        float r2v[8];
        #pragma unroll
        for (int i = 0; i < 8; i++) r2v[i] = r2s[ty * 8 + i];

        float bestS[8];
        int   bestK[8];
        #pragma unroll
        for (int i = 0; i < 8; i++) { bestS[i] = 3.4e38f; bestK[i] = 0; }

        for (int ch = 0; ch < Kk / KCH; ++ch) {
            if (ch + 1 < Kk / KCH) {
                const float* srcb = cbg + (size_t)(ch + 1) * KCH * Dd;
                uint32_t cbo = ((ch + 1) & 1) ? cboff1 : cboff0;
                for (int e = tid; e < KCH * (Dd / 4); e += THREADS) {
                    int kk = e >> 5, d4 = e & 31;
                    uint32_t dst = sbase + cbo + (uint32_t)(kk * RS + d4 * 4) * 4u;
                    CP16(dst, srcb + (size_t)kk * Dd + d4 * 4);
                }
                CP_COMMIT();
                CP_WAIT(1);
            } else {
                CP_WAIT(0);
            }
            __syncthreads();

            // ---- 8 tokens x 4 codes: ascending-d single-chain FMA dots ----
            float acc[8][4];
            #pragma unroll
            for (int i = 0; i < 8; i++)
                #pragma unroll
                for (int j = 0; j < 4; j++) acc[i][j] = 0.f;

            const float* rbase = res + roff(ty * 8);
            const float* cbb   = sm + ((ch & 1) ? (RES_FLOATS + CB_FLOATS)
                                                : RES_FLOATS) + tx * 4 * RS;

            #pragma unroll 4
            for (int d = 0; d < Dd; d += 4) {
                float4 c4[4], r4[8];
                #pragma unroll
                for (int j = 0; j < 4; j++)
                    c4[j] = *(const float4*)(cbb + j * RS + d);
                #pragma unroll
                for (int i = 0; i < 8; i++)
                    r4[i] = *(const float4*)(rbase + i * RS + d);
                #pragma unroll
                for (int i = 0; i < 8; i++)
                    #pragma unroll
                    for (int j = 0; j < 4; j++) {
                        float a = acc[i][j];
                        a = __fmaf_rn(r4[i].x, c4[j].x, a);
                        a = __fmaf_rn(r4[i].y, c4[j].y, a);
                        a = __fmaf_rn(r4[i].z, c4[j].z, a);
                        a = __fmaf_rn(r4[i].w, c4[j].w, a);
                        acc[i][j] = a;
                    }
            }

            const int kbase = ch * KCH + tx * 4;
            #pragma unroll
            for (int j = 0; j < 4; j++) {
                float c2 = __ldg(&g_c2[stage * Kk + kbase + j]);
                #pragma unroll
                for (int i = 0; i < 8; i++) {
                    // d2 = (r2 - 2*cross) + c2, reference op order
                    float s = __fadd_rn(
                        __fsub_rn(r2v[i], __fmul_rn(2.0f, acc[i][j])), c2);
                    if (s < bestS[i]) { bestS[i] = s; bestK[i] = kbase + j; }
                }
            }
            __syncthreads();
        }

        // ---- argmin across the 16 tx lanes (min value, lowest index) ----
        #pragma unroll
        for (int i = 0; i < 8; i++) {
            float s = bestS[i];
            int   k = bestK[i];
            #pragma unroll
            for (int m = 8; m >= 1; m >>= 1) {
                float s2 = __shfl_xor_sync(0xffffffffu, s, m);
                int   k2 = __shfl_xor_sync(0xffffffffu, k, m);
                if (s2 < s || (s2 == s && k2 < k)) { s = s2; k = k2; }
            }
            if (tx == 0) idxAll[stage * MT + ty * 8 + i] = k;
        }
        __syncthreads();

        // ---- gather winner, update residual (exact fsub), loss ----
        {
            int t  = tid >> 1;
            int d0 = (tid & 1) * 64;
            int k  = idxAll[stage * MT + t];
            const float4* cw = (const float4*)(cbg + (size_t)k * Dd + d0);
            float* rr = res + roff(t) + d0;
            #pragma unroll
            for (int u = 0; u < 16; u++) {
                float4 q = __ldg(&cw[u]);
                float4 r = *(float4*)(rr + u * 4);
                r.x = __fsub_rn(r.x, q.x);
                r.y = __fsub_rn(r.y, q.y);
                r.z = __fsub_rn(r.z, q.z);
                r.w = __fsub_rn(r.w, q.w);
                *(float4*)(rr + u * 4) = r;
                lossAcc += r.x * r.x + r.y * r.y + r.z * r.z + r.w * r.w;
            }
            if (has_idx && (tid & 1) == 0)
                out_idx[(size_t)(tokBase + t) * Qq + stage] = (float)k;
        }
        __syncthreads();
    }

    // ---- quantized: stage-ordered adds of gathered codewords, then STE ----
    {
        const float* xf = x + (size_t)tokBase * Dd;
        float* oq = out_q + (size_t)tokBase * Dd;
        for (int e = tid; e < MT * Dd; e += THREADS) {
            int t = e >> 7, d = e & 127;
            float q = 0.f;
            #pragma unroll
            for (int s = 0; s < Qq; s++) {
                const float* cbg = cbks + (size_t)s * Kk * Dd;
                int k = idxAll[s * MT + t];
                q = __fadd_rn(q, __ldg(&cbg[(size_t)k * Dd + d]));
            }
            float xv = xf[e];
            oq[e] = __fadd_rn(xv, __fsub_rn(q, xv));
        }
    }

    // ---- per-CTA loss partial ----
    #pragma unroll
    for (int m = 16; m >= 1; m >>= 1)
        lossAcc += __shfl_xor_sync(0xffffffffu, lossAcc, m);
    if (lane == 0) wsum[tid >> 5] = lossAcc;
    __syncthreads();
    if (tid == 0) {
        float s = 0.f;
        #pragma unroll
        for (int w = 0; w < THREADS / 32; w++) s += wsum[w];
        g_partials[cta] = s;
    }
}

// ---------------------------------------------------------------------------
// Deterministic final loss reduction
// ---------------------------------------------------------------------------
__global__ void loss_reduce(float* __restrict__ out, int off, int n, float scale) {
    __shared__ float s[512];
    int tid = threadIdx.x;
    float v = 0.f;
    for (int i = tid; i < n; i += 512) v += g_partials[i];
    s[tid] = v;
    __syncthreads();
    for (int m = 256; m >= 1; m >>= 1) {
        if (tid < m) s[tid] += s[tid + m];
        __syncthreads();
    }
    if (tid == 0) out[off] = s[0] * scale;
}

// ---------------------------------------------------------------------------
extern "C" void kernel_launch(void* const* d_in, const int* in_sizes, int n_in,
                              void* d_out, int out_size) {
    int xi = 0, ci = 1;
    if (n_in >= 2 && in_sizes[0] < in_sizes[1]) { xi = 1; ci = 0; }  // defensive
    const float* x  = (const float*)d_in[xi];
    const float* cb = (const float*)d_in[ci];
    float* out = (float*)d_out;

    const int q_elems   = in_sizes[xi];          // B*S*D
    const int tokens    = q_elems / Dd;          // B*S
    const int idx_elems = tokens * Qq;
    const int grid      = tokens / MT;

    const int has_idx  = (out_size >= q_elems + idx_elems) ? 1 : 0;
    const int has_loss = (out_size >= q_elems + idx_elems + 1) ? 1 : 0;

    cudaFuncSetAttribute(rvq_kernel,
                         cudaFuncAttributeMaxDynamicSharedMemorySize, SMEM_BYTES);

    c2_kernel<<<(Qq * Kk * 32 + 255) / 256, 256>>>(cb);
    rvq_kernel<<<grid, THREADS, SMEM_BYTES>>>(
        x, cb, out, out + q_elems, has_idx);
    if (has_loss)
        loss_reduce<<<1, 512>>>(out, q_elems + idx_elems, grid,
                                0.25f / (float)q_elems);
}

// round 4
// speedup vs baseline: 1.3734x; 1.3734x over previous
#include <cuda_runtime.h>
#include <cstdint>
#include <cstddef>

// Residual Vector Quantizer: B=16,S=4096,D=128, Q=4 stages, K=512 codes.
// Bit-exact replication of the reference (rel_err 0.0 in R3), now with
// fma.rn.f32x2: each half is an independent ascending-d IEEE fp32 FMA chain
// (token i x code j), bit-identical to scalar __fmaf_rn chains, 2x FLOP/cyc.
//
//   codebook in smem: interleaved pair rows (c_j0d, c_j1d, c_j0d1, c_j1d1,...)
//   residual in smem: duplicated (r_d, r_d) so one 16B LDS = 2 dims of pairs
//
// Output buffer layout (float32):
//   [0, BSD)        quantized
//   [BSD, BSD+BSQ)  indices (as float)
//   [BSD+BSQ]       commitment loss * 0.25

#define Dd      128
#define Kk      512
#define Qq      4
#define MT      128   // tokens per CTA
#define KCH     64    // codewords per chunk
#define RDS     260   // duplicated residual row stride (floats); 1040B
#define PRS     260   // codebook pair-row stride (floats); 1040B
#define THREADS 256
#define MAXGRID 1024

// smem layout (floats)
#define RESD_FLOATS (MT * RDS)                  // 33280
#define CBUF_FLOATS (32 * PRS)                  // 8320
#define CB0_OFF     RESD_FLOATS                 // 33280
#define CB1_OFF     (CB0_OFF + CBUF_FLOATS)     // 41600
#define IDX_OFF     (CB1_OFF + CBUF_FLOATS)     // 49920 (512 ints)
#define R2_OFF      (IDX_OFF + 512)             // 50432
#define WSUM_OFF    (R2_OFF + 128)              // 50560
#define SMEM_FLOATS (WSUM_OFF + 8)              // 50568
#define SMEM_BYTES  (SMEM_FLOATS * 4)           // 202272 B

__device__ __align__(16) float g_c2[Qq * Kk];
__device__ float g_partials[MAXGRID];

__device__ __forceinline__ void lds_v2u64(uint64_t& a, uint64_t& b, uint32_t addr) {
    asm volatile("ld.shared.v2.u64 {%0,%1},[%2];" : "=l"(a), "=l"(b) : "r"(addr));
}
__device__ __forceinline__ void ffma2(uint64_t& acc, uint64_t a, uint64_t b) {
    asm volatile("fma.rn.f32x2 %0,%1,%2,%0;" : "+l"(acc) : "l"(a), "l"(b));
}
__device__ __forceinline__ void unpack2(float& lo, float& hi, uint64_t v) {
    asm volatile("mov.b64 {%0,%1},%2;" : "=f"(lo), "=f"(hi) : "l"(v));
}
__device__ __forceinline__ void sts_dup(uint32_t addr, float v) {
    asm volatile("st.shared.v2.f32 [%0],{%1,%1};" :: "r"(addr), "f"(v));
}
__device__ __forceinline__ void sts128(uint32_t addr, float a, float b, float c, float d) {
    asm volatile("st.shared.v4.f32 [%0],{%1,%2,%3,%4};"
                 :: "r"(addr), "f"(a), "f"(b), "f"(c), "f"(d));
}
__device__ __forceinline__ float lds32(uint32_t addr) {
    float v;
    asm volatile("ld.shared.f32 %0,[%1];" : "=f"(v) : "r"(addr));
    return v;
}

// ---------------------------------------------------------------------------
// c2[q*K+k] = XLA-ordered sum of squares of codebook row. One warp per row.
// ---------------------------------------------------------------------------
__global__ void c2_kernel(const float* __restrict__ cbks) {
    int warp = (blockIdx.x * blockDim.x + threadIdx.x) >> 5;
    int lane = threadIdx.x & 31;
    if (warp < Qq * Kk) {
        const float2* p2 = (const float2*)(cbks + (size_t)warp * Dd);
        float2 a = p2[lane];
        float2 b = p2[lane + 32];
        float p0 = __fmul_rn(a.x, a.x);
        float p1 = __fmul_rn(a.y, a.y);
        float q0 = __fmul_rn(b.x, b.x);
        float q1 = __fmul_rn(b.y, b.y);
        float part = __fadd_rn(__fadd_rn(p0, q0), __fadd_rn(p1, q1));
        #pragma unroll
        for (int off = 16; off >= 1; off >>= 1)
            part = __fadd_rn(part, __shfl_down_sync(0xffffffffu, part, off));
        if (lane == 0) g_c2[warp] = part;
    }
}

// ---------------------------------------------------------------------------
// Codebook chunk staging: LDG into regs (prefetch), later STS interleaved.
// Warp w handles phys rows rho = w + 8k (k=0..3).
// Phys row rho holds pair p: rho<16 -> p=2*rho (even pairs), else p=2*(rho-16)+1.
// Pair p = chunk-local codes (2p, 2p+1), interleaved by dim.
// ---------------------------------------------------------------------------
__device__ __forceinline__ void stage_ldg(
    const float* __restrict__ cbg, int ch, int w, int lane,
    float2 (&a0)[4], float2 (&a1)[4], float2 (&b0)[4], float2 (&b1)[4])
{
    #pragma unroll
    for (int k = 0; k < 4; k++) {
        int rho = w + 8 * k;
        int p   = (rho < 16) ? (rho * 2) : ((rho - 16) * 2 + 1);
        const float* g0 = cbg + (size_t)(ch * KCH + 2 * p) * Dd;
        const float* g1 = g0 + Dd;
        a0[k] = __ldg((const float2*)(g0 + 2 * lane));
        a1[k] = __ldg((const float2*)(g1 + 2 * lane));
        b0[k] = __ldg((const float2*)(g0 + 2 * lane + 64));
        b1[k] = __ldg((const float2*)(g1 + 2 * lane + 64));
    }
}
__device__ __forceinline__ void stage_sts(
    uint32_t cbuf, int w, int lane,
    const float2 (&a0)[4], const float2 (&a1)[4],
    const float2 (&b0)[4], const float2 (&b1)[4])
{
    #pragma unroll
    for (int k = 0; k < 4; k++) {
        int rho = w + 8 * k;
        uint32_t base = cbuf + (uint32_t)(rho * PRS) * 4u + (uint32_t)lane * 16u;
        sts128(base,        a0[k].x, a1[k].x, a0[k].y, a1[k].y);
        sts128(base + 512u, b0[k].x, b1[k].x, b0[k].y, b1[k].y);
    }
}

// ---------------------------------------------------------------------------
// Main RVQ kernel. One CTA = 128 tokens, all 4 stages.
// ---------------------------------------------------------------------------
__global__ void __launch_bounds__(THREADS, 1)
rvq_kernel(const float* __restrict__ x, const float* __restrict__ cbks,
           float* __restrict__ out_q, float* __restrict__ out_idx, int has_idx)
{
    extern __shared__ float sm[];
    const int tid     = threadIdx.x;
    const int lane    = tid & 31;
    const int w       = tid >> 5;
    const int cta     = blockIdx.x;
    const int tokBase = cta * MT;

    int*   idxAll = (int*)(sm + IDX_OFF);
    float* r2s    = sm + R2_OFF;
    float* wsum   = sm + WSUM_OFF;
    const uint32_t sbase = (uint32_t)__cvta_generic_to_shared(sm);
    const uint32_t cbB0  = sbase + (uint32_t)CB0_OFF * 4u;
    const uint32_t cbB1  = sbase + (uint32_t)CB1_OFF * 4u;

    // Load x tile into duplicated residual layout
    const float4* x4 = (const float4*)(x + (size_t)tokBase * Dd);
    for (int e = tid; e < MT * (Dd / 4); e += THREADS) {
        int t = e >> 5, d4 = e & 31;
        float4 v = x4[e];
        uint32_t a = sbase + (uint32_t)(t * RDS) * 4u + (uint32_t)d4 * 32u;
        sts_dup(a, v.x); sts_dup(a + 8, v.y); sts_dup(a + 16, v.z); sts_dup(a + 24, v.w);
    }
    __syncthreads();

    const int ty = tid >> 4;   // token group 0..15 (8 tokens each)
    const int tx = tid & 15;   // code group (4 codes = 2 pairs)
    const uint32_t rb   = sbase + (uint32_t)((ty * 8) * RDS) * 4u;
    const uint32_t cbrA = (uint32_t)(tx * PRS) * 4u;          // phys row tx  (pair 2tx)
    const uint32_t cbrB = (uint32_t)((16 + tx) * PRS) * 4u;   // phys row 16+tx (pair 2tx+1)
    float lossAcc = 0.f;

    for (int stage = 0; stage < Qq; ++stage) {
        const float* cbg = cbks + (size_t)stage * Kk * Dd;

        // prefetch chunk 0 (LDG latency hidden under r2 phase)
        float2 pa0[4], pa1[4], pb0[4], pb1[4];
        stage_ldg(cbg, 0, w, lane, pa0, pa1, pb0, pb1);

        // ---- r2 per token, XLA row-reduce order (reads lo copies) ----
        for (int it = 0; it < 16; ++it) {
            int t = w * 16 + it;
            const float* row = sm + t * RDS;
            float a0 = row[4 * lane],       a1 = row[4 * lane + 2];
            float b0 = row[4 * lane + 128], b1 = row[4 * lane + 130];
            float p0 = __fmul_rn(a0, a0);
            float p1 = __fmul_rn(a1, a1);
            float q0 = __fmul_rn(b0, b0);
            float q1 = __fmul_rn(b1, b1);
            float part = __fadd_rn(__fadd_rn(p0, q0), __fadd_rn(p1, q1));
            #pragma unroll
            for (int off = 16; off >= 1; off >>= 1)
                part = __fadd_rn(part, __shfl_down_sync(0xffffffffu, part, off));
            if (lane == 0) r2s[t] = part;
        }

        stage_sts(cbB0, w, lane, pa0, pa1, pb0, pb1);
        __syncthreads();

        float r2v[8];
        #pragma unroll
        for (int i = 0; i < 8; i++) r2v[i] = r2s[ty * 8 + i];

        float bestS[8];
        int   bestK[8];
        #pragma unroll
        for (int i = 0; i < 8; i++) { bestS[i] = 3.4e38f; bestK[i] = 0; }

        for (int ch = 0; ch < Kk / KCH; ++ch) {
            if (ch + 1 < Kk / KCH)
                stage_ldg(cbg, ch + 1, w, lane, pa0, pa1, pb0, pb1);

            const uint32_t cbase = (ch & 1) ? cbB1 : cbB0;
            const uint32_t cA = cbase + cbrA;
            const uint32_t cB = cbase + cbrB;

            // ---- 8 tokens x 4 codes (2 FFMA2 pairs), ascending-d chains ----
            uint64_t acc[8][2];
            #pragma unroll
            for (int i = 0; i < 8; i++) { acc[i][0] = 0ull; acc[i][1] = 0ull; }

            #pragma unroll 4
            for (int d = 0; d < Dd; d += 2) {
                uint64_t cc00, cc01, cc10, cc11;
                lds_v2u64(cc00, cc01, cA + (uint32_t)d * 8u);
                lds_v2u64(cc10, cc11, cB + (uint32_t)d * 8u);
                uint64_t rr0[8], rr1[8];
                #pragma unroll
                for (int i = 0; i < 8; i++)
                    lds_v2u64(rr0[i], rr1[i],
                              rb + (uint32_t)(i * RDS) * 4u + (uint32_t)d * 8u);
                #pragma unroll
                for (int i = 0; i < 8; i++) {
                    ffma2(acc[i][0], rr0[i], cc00);
                    ffma2(acc[i][0], rr1[i], cc01);
                    ffma2(acc[i][1], rr0[i], cc10);
                    ffma2(acc[i][1], rr1[i], cc11);
                }
            }

            const int kbase = ch * KCH + tx * 4;
            float4 c2v = __ldg((const float4*)&g_c2[stage * Kk + kbase]);
            #pragma unroll
            for (int i = 0; i < 8; i++) {
                float lo, hi;
                unpack2(lo, hi, acc[i][0]);
                float s0 = __fadd_rn(__fsub_rn(r2v[i], __fmul_rn(2.0f, lo)), c2v.x);
                if (s0 < bestS[i]) { bestS[i] = s0; bestK[i] = kbase; }
                float s1 = __fadd_rn(__fsub_rn(r2v[i], __fmul_rn(2.0f, hi)), c2v.y);
                if (s1 < bestS[i]) { bestS[i] = s1; bestK[i] = kbase + 1; }
                unpack2(lo, hi, acc[i][1]);
                float s2 = __fadd_rn(__fsub_rn(r2v[i], __fmul_rn(2.0f, lo)), c2v.z);
                if (s2 < bestS[i]) { bestS[i] = s2; bestK[i] = kbase + 2; }
                float s3 = __fadd_rn(__fsub_rn(r2v[i], __fmul_rn(2.0f, hi)), c2v.w);
                if (s3 < bestS[i]) { bestS[i] = s3; bestK[i] = kbase + 3; }
            }

            if (ch + 1 < Kk / KCH)
                stage_sts((ch & 1) ? cbB0 : cbB1, w, lane, pa0, pa1, pb0, pb1);
            __syncthreads();
        }

        // ---- argmin across the 16 tx lanes (min value, lowest index) ----
        #pragma unroll
        for (int i = 0; i < 8; i++) {
            float s = bestS[i];
            int   k = bestK[i];
            #pragma unroll
            for (int m = 8; m >= 1; m >>= 1) {
                float s2 = __shfl_xor_sync(0xffffffffu, s, m);
                int   k2 = __shfl_xor_sync(0xffffffffu, k, m);
                if (s2 < s || (s2 == s && k2 < k)) { s = s2; k = k2; }
            }
            if (tx == 0) idxAll[stage * MT + ty * 8 + i] = k;
        }
        __syncthreads();

        // ---- gather winner, update residual (exact fsub, both copies), loss ----
        {
            int t = tid >> 1;
            int h = tid & 1;
            int k = idxAll[stage * MT + t];
            const float4* cw = (const float4*)(cbg + (size_t)k * Dd + h * 64);
            uint32_t rrow = sbase + (uint32_t)(t * RDS) * 4u + (uint32_t)h * 512u;
            #pragma unroll
            for (int u = 0; u < 16; u++) {
                float4 q = __ldg(&cw[u]);
                uint32_t a = rrow + (uint32_t)u * 32u;
                float r0 = lds32(a);
                float r1 = lds32(a + 8);
                float r2_ = lds32(a + 16);
                float r3 = lds32(a + 24);
                r0 = __fsub_rn(r0, q.x);
                r1 = __fsub_rn(r1, q.y);
                r2_ = __fsub_rn(r2_, q.z);
                r3 = __fsub_rn(r3, q.w);
                sts_dup(a, r0); sts_dup(a + 8, r1);
                sts_dup(a + 16, r2_); sts_dup(a + 24, r3);
                lossAcc += r0 * r0 + r1 * r1 + r2_ * r2_ + r3 * r3;
            }
            if (has_idx && h == 0)
                out_idx[(size_t)(tokBase + t) * Qq + stage] = (float)k;
        }
        __syncthreads();
    }

    // ---- quantized: stage-ordered adds of gathered codewords, then STE ----
    {
        const float* xf = x + (size_t)tokBase * Dd;
        float* oq = out_q + (size_t)tokBase * Dd;
        for (int e = tid; e < MT * Dd; e += THREADS) {
            int t = e >> 7, d = e & 127;
            float q = 0.f;
            #pragma unroll
            for (int s = 0; s < Qq; s++) {
                const float* cbg = cbks + (size_t)s * Kk * Dd;
                int k = idxAll[s * MT + t];
                q = __fadd_rn(q, __ldg(&cbg[(size_t)k * Dd + d]));
            }
            float xv = xf[e];
            oq[e] = __fadd_rn(xv, __fsub_rn(q, xv));
        }
    }

    // ---- per-CTA loss partial ----
    #pragma unroll
    for (int m = 16; m >= 1; m >>= 1)
        lossAcc += __shfl_xor_sync(0xffffffffu, lossAcc, m);
    if (lane == 0) wsum[w] = lossAcc;
    __syncthreads();
    if (tid == 0) {
        float s = 0.f;
        #pragma unroll
        for (int wi = 0; wi < THREADS / 32; wi++) s += wsum[wi];
        g_partials[cta] = s;
    }
}

// ---------------------------------------------------------------------------
// Deterministic final loss reduction
// ---------------------------------------------------------------------------
__global__ void loss_reduce(float* __restrict__ out, int off, int n, float scale) {
    __shared__ float s[512];
    int tid = threadIdx.x;
    float v = 0.f;
    for (int i = tid; i < n; i += 512) v += g_partials[i];
    s[tid] = v;
    __syncthreads();
    for (int m = 256; m >= 1; m >>= 1) {
        if (tid < m) s[tid] += s[tid + m];
        __syncthreads();
    }
    if (tid == 0) out[off] = s[0] * scale;
}

// ---------------------------------------------------------------------------
extern "C" void kernel_launch(void* const* d_in, const int* in_sizes, int n_in,
                              void* d_out, int out_size) {
    int xi = 0, ci = 1;
    if (n_in >= 2 && in_sizes[0] < in_sizes[1]) { xi = 1; ci = 0; }  // defensive
    const float* x  = (const float*)d_in[xi];
    const float* cb = (const float*)d_in[ci];
    float* out = (float*)d_out;

    const int q_elems   = in_sizes[xi];          // B*S*D
    const int tokens    = q_elems / Dd;          // B*S
    const int idx_elems = tokens * Qq;
    const int grid      = tokens / MT;

    const int has_idx  = (out_size >= q_elems + idx_elems) ? 1 : 0;
    const int has_loss = (out_size >= q_elems + idx_elems + 1) ? 1 : 0;

    cudaFuncSetAttribute(rvq_kernel,
                         cudaFuncAttributeMaxDynamicSharedMemorySize, SMEM_BYTES);

    c2_kernel<<<(Qq * Kk * 32 + 255) / 256, 256>>>(cb);
    rvq_kernel<<<grid, THREADS, SMEM_BYTES>>>(
        x, cb, out, out + q_elems, has_idx);
    if (has_loss)
        loss_reduce<<<1, 512>>>(out, q_elems + idx_elems, grid,
                                0.25f / (float)q_elems);
}